// round 9
// baseline (speedup 1.0000x reference)
#include <cuda_runtime.h>
#include <math.h>

// ----------------------------------------------------------------------------
// margin ranking loss (all i<j pairs) + weighted BCE, B=8192, labels in {0,1}.
//   equal-label pairs: relu(m) each -> closed form from n1
//   mixed pairs:       relu((m + p_neg) - p_pos)
// Exact binned algorithm, c = m+p_neg and a = p_pos on one 256-bin grid:
//   bin(c) > bin(a)  -> contributes (c - a) -> smem suffix count/sum, O(1)/a
//   bin(c) == bin(a) -> exact relu vs SMEM-compacted bin list (~80 items)
//   bin(c) < bin(a)  -> 0
// Edge bins open-ended + overflow list exact-evaluated -> exact for any data.
// ----------------------------------------------------------------------------

#define T1   256
#define T2   256
#define MAXB 8192
#define NBIN 256
#define CAP  128
#define BLO  (-6.0f)
#define BHI  (7.0f)
#define INVW ((float)NBIN / (BHI - BLO))
#define MAXG 64

// scratch (allocation-free rule: __device__ globals)
__device__ int      g_bc[NBIN];            // bin attempt counts
__device__ float    g_bs[NBIN];            // bin sums (stored items only)
__device__ float    g_bins[NBIN * CAP];    // stored c values per bin
__device__ float    g_ovf[MAXB];           // overflow list (normally empty)
__device__ int      g_ovfCnt = 0;
__device__ int      g_n1     = 0;
__device__ double   g_bceB[MAXG];
__device__ double   g_mixB[MAXG];
__device__ unsigned g_done   = 0;

__device__ __forceinline__ float read_margin(const void* p) {
    if (p == nullptr) return 1.0f;
    int v = *(const int*)p;
    if (v >= -1000000 && v <= 1000000) return (float)v;   // int scalar
    return __int_as_float(v);                             // float bits
}

__device__ __forceinline__ int bin_of(float x) {
    int b = (int)floorf((x - BLO) * INVW);
    return max(0, min(NBIN - 1, b));
}

// ---------------------------------------------------------------------------
// Kernel 1: BCE partials, n1 count, binned scatter of c = m + p_neg.
// ---------------------------------------------------------------------------
__global__ void __launch_bounds__(T1)
k1(const float* __restrict__ preds,  const float* __restrict__ labels,
   const float* __restrict__ logits, const float* __restrict__ targets,
   const float* __restrict__ pw_, int n, const void* __restrict__ marginp)
{
    const int tid  = threadIdx.x;
    const int lane = tid & 31, w = tid >> 5;
    const int i    = blockIdx.x * T1 + tid;
    const float m  = read_margin(marginp);
    const float pw = pw_[0];

    float p = 0.f, bce = 0.f;
    bool pos = false, neg = false;
    if (i < n) {
        p = preds[i];
        const bool fl = (labels[i] > 0.5f);
        pos = fl; neg = !fl;
        const float x  = logits[i];
        const float t  = targets[i];
        const float mv = fmaxf(-x, 0.0f);
        const float sp = __logf(__expf(-mv) + __expf(-x - mv)) + mv;
        bce = (1.0f - t) * x + (1.0f + (pw - 1.0f) * t) * sp;
    }

    // n1: one atomic per warp
    const unsigned bp = __ballot_sync(0xffffffffu, pos);
    if (lane == 0 && bp) atomicAdd(&g_n1, __popc(bp));

    // binned scatter (order in bin irrelevant: sums commute)
    if (neg) {
        const float c  = m + p;
        const int   ib = bin_of(c);
        const int  idx = atomicAdd(&g_bc[ib], 1);
        if (idx < CAP) {
            g_bins[ib * CAP + idx] = c;
            atomicAdd(&g_bs[ib], c);
        } else {
            const int oi = atomicAdd(&g_ovfCnt, 1);
            if (oi < MAXB) g_ovf[oi] = c;
        }
    }

    // BCE block reduce -> one plain store per block
    double d = (double)bce;
    #pragma unroll
    for (int off = 16; off; off >>= 1)
        d += __shfl_down_sync(0xffffffffu, d, off);
    __shared__ double wb[8];
    if (lane == 0) wb[w] = d;
    __syncthreads();
    if (tid == 0) {
        double s = 0.0;
        #pragma unroll
        for (int k = 0; k < 8; k++) s += wb[k];
        g_bceB[blockIdx.x] = s;
    }
}

// ---------------------------------------------------------------------------
// Kernel 2: compact bins into SMEM, suffix count/sum scan in SMEM, per-pos
// closed form + per-thread exact same-bin eval from SMEM. Last block final.
// ---------------------------------------------------------------------------
__global__ void __launch_bounds__(T2)
k2(const float* __restrict__ preds, const float* __restrict__ labels,
   int n, const void* __restrict__ marginp, float* __restrict__ out)
{
    __shared__ float  sval[MAXB];          // compacted stored c values
    __shared__ int    scnt[NBIN];          // stored count per bin
    __shared__ int    soff[NBIN + 1];      // exclusive prefix of scnt
    __shared__ double sufS[NBIN + 1];      // suffix sum of bin value-sums
    __shared__ int    sufC[NBIN + 1];      // suffix count
    __shared__ double wred[8];
    __shared__ int    isLast;

    const int tid  = threadIdx.x;
    const int lane = tid & 31, w = tid >> 5;
    const float m  = read_margin(marginp);

    // ---- load per-bin counts/sums, combined prefix(off)+suffix(S,C) scans --
    double myS = 0.0; int myC = 0;
    if (tid < NBIN) {
        myC = min(g_bc[tid], CAP);
        myS = (double)g_bs[tid];
        scnt[tid] = myC;
        soff[tid] = myC;                    // will become inclusive prefix
        sufS[tid] = myS;
        sufC[tid] = myC;
    }
    if (tid == 0) { sufS[NBIN] = 0.0; sufC[NBIN] = 0; }
    __syncthreads();
    // Hillis-Steele: prefix on soff (inclusive), suffix on sufS/sufC
    for (int off = 1; off < NBIN; off <<= 1) {
        int    pv = 0;  double vS = 0.0;  int vC = 0;
        if (tid < NBIN) {
            if (tid >= off)        pv = soff[tid - off];
            if (tid + off < NBIN) { vS = sufS[tid + off]; vC = sufC[tid + off]; }
        }
        __syncthreads();
        if (tid < NBIN) { soff[tid] += pv; sufS[tid] += vS; sufC[tid] += vC; }
        __syncthreads();
    }
    // convert inclusive prefix -> exclusive base offsets (reuse scnt)
    __shared__ int ebase[NBIN];
    if (tid < NBIN) ebase[tid] = soff[tid] - scnt[tid];
    __syncthreads();

    // ---- compact stored values into smem (flat predicated copy) -----------
    for (int s = tid; s < NBIN * CAP; s += T2) {
        const int b = s >> 7;               // CAP == 128
        const int j = s & (CAP - 1);
        if (j < scnt[b]) sval[ebase[b] + j] = g_bins[s];
    }
    __syncthreads();

    // ---- per-element phase -------------------------------------------------
    const int i = blockIdx.x * T2 + tid;
    double dacc = 0.0;
    if (i < n && labels[i] > 0.5f) {
        const float a  = preds[i];
        const int   ka = bin_of(a);
        // all strictly-higher bins: sum(c) - a*count  (c >= a guaranteed)
        dacc = sufS[ka + 1] - (double)a * (double)sufC[ka + 1];
        // same-bin exact eval from smem (~80 items, pipelined LDS)
        const int b0 = ebase[ka], c0 = scnt[ka];
        float part = 0.f;
        for (int j = 0; j < c0; j++)
            part += fmaxf(sval[b0 + j] - a, 0.f);
        // overflow list (normally empty)
        const int oc = min(g_ovfCnt, MAXB);
        for (int j = 0; j < oc; j++)
            part += fmaxf(g_ovf[j] - a, 0.f);
        dacc += (double)part;
    }

    // ---- block reduce + publish -------------------------------------------
    #pragma unroll
    for (int off = 16; off; off >>= 1)
        dacc += __shfl_down_sync(0xffffffffu, dacc, off);
    if (lane == 0) wred[w] = dacc;
    __syncthreads();
    if (tid == 0) {
        double s = 0.0;
        #pragma unroll
        for (int k = 0; k < 8; k++) s += wred[k];
        g_mixB[blockIdx.x] = s;
        __threadfence();
        isLast = (atomicAdd(&g_done, 1u) == gridDim.x - 1u) ? 1 : 0;
    }
    __syncthreads();

    // ---- last block: finalize + reset -------------------------------------
    if (isLast) {
        const int gb = gridDim.x;
        double fm = 0.0, fb = 0.0;
        for (int j = tid; j < gb; j += T2) {
            fm += __ldcg(&g_mixB[j]);
            fb += __ldcg(&g_bceB[j]);
        }
        #pragma unroll
        for (int off = 16; off; off >>= 1) {
            fm += __shfl_down_sync(0xffffffffu, fm, off);
            fb += __shfl_down_sync(0xffffffffu, fb, off);
        }
        __shared__ double zm[8], zb[8];
        if (lane == 0) { zm[w] = fm; zb[w] = fb; }
        __syncthreads();
        if (tid == 0) {
            double sm = 0.0, sb = 0.0;
            #pragma unroll
            for (int k = 0; k < 8; k++) { sm += zm[k]; sb += zb[k]; }
            const int    n1  = g_n1;
            const double dn1 = (double)n1, dn0 = (double)(n - n1);
            const double eqPairs = 0.5 * (dn1 * (dn1 - 1.0) + dn0 * (dn0 - 1.0));
            const double mm = (m > 0.0f) ? (double)m : 0.0;
            out[0] = (float)((mm * eqPairs + sm) / (double)n);
            out[1] = (float)(sb / (double)n);
        }
        __syncthreads();
        // reset persistent state for next graph replay
        for (int j = tid; j < NBIN; j += T2) { g_bc[j] = 0; g_bs[j] = 0.f; }
        if (tid == 0) { g_ovfCnt = 0; g_n1 = 0; g_done = 0u; }
    }
}

// ---------------------------------------------------------------------------
extern "C" void kernel_launch(void* const* d_in, const int* in_sizes, int n_in,
                              void* d_out, int out_size)
{
    const float* preds   = (const float*)d_in[0];
    const float* labels  = (const float*)d_in[1];
    const float* logits  = (const float*)d_in[2];
    const float* targets = (const float*)d_in[3];
    const float* pw      = (const float*)d_in[4];
    const void*  marginp = (n_in >= 6) ? d_in[5] : nullptr;
    const int n = in_sizes[0];
    float* out = (float*)d_out;

    const int g = min((n + T1 - 1) / T1, MAXG);
    k1<<<g, T1>>>(preds, labels, logits, targets, pw, n, marginp);
    k2<<<g, T2>>>(preds, labels, n, marginp, out);
}

// round 11
// speedup vs baseline: 1.7247x; 1.7247x over previous
#include <cuda_runtime.h>
#include <math.h>

// ----------------------------------------------------------------------------
// margin ranking loss (all i<j pairs) + weighted BCE, B=8192, labels in {0,1}.
//   equal-label pairs: relu(m) each -> closed form from n1
//   mixed pairs:       relu((m + p_neg) - p_pos)
// Exact binned algorithm on a 256-bin grid (clamped edge bins):
//   bin(c) > bin(a)  -> contributes (c - a)   -> global suffix count/sum, O(1)/a
//   bin(c) == bin(a) -> exact relu vs bin list (~16 items avg, L2-hot)
//   bin(c) < bin(a)  -> 0
// Overflowing bins spill to an exact-eval list -> exact for any input.
// k1: BCE + n1 + binned scatter; its LAST block computes the suffix scan.
// k2: pure per-element eval + final reduction/outputs/reset.
// ----------------------------------------------------------------------------

#define T1   256
#define G1MAX 64
#define T2   128
#define G2MAX 64
#define MAXB 8192
#define NBIN 256
#define CAP  128
#define BLO  (-6.0f)
#define BHI  (7.0f)
#define INVW ((float)NBIN / (BHI - BLO))

// scratch (allocation-free rule: __device__ globals)
__device__ int      g_bc[NBIN];            // bin attempt counts
__device__ float    g_bs[NBIN];            // bin sums (stored items only)
__device__ float    g_bins[NBIN * CAP];    // stored c values per bin
__device__ float    g_ovf[MAXB];           // overflow list (normally empty)
__device__ int      g_ovfCnt = 0;
__device__ int      g_n1     = 0;
__device__ double   g_sufS[NBIN + 1];      // suffix sums; [NBIN] stays 0 (static init)
__device__ int      g_sufC[NBIN + 1];      // suffix counts; [NBIN] stays 0
__device__ double   g_bceB[G1MAX];
__device__ double   g_mixB[G2MAX];
__device__ unsigned g_done1  = 0;
__device__ unsigned g_done2  = 0;

__device__ __forceinline__ float read_margin(const void* p) {
    if (p == nullptr) return 1.0f;
    int v = *(const int*)p;
    if (v >= -1000000 && v <= 1000000) return (float)v;   // int scalar
    return __int_as_float(v);                             // float bits
}

__device__ __forceinline__ int bin_of(float x) {
    int b = (int)floorf((x - BLO) * INVW);
    return max(0, min(NBIN - 1, b));
}

// ---------------------------------------------------------------------------
// Kernel 1: BCE partials, n1, binned scatter; last block: suffix scan.
// ---------------------------------------------------------------------------
__global__ void __launch_bounds__(T1)
k1(const float* __restrict__ preds,  const float* __restrict__ labels,
   const float* __restrict__ logits, const float* __restrict__ targets,
   const float* __restrict__ pw_, int n, const void* __restrict__ marginp)
{
    const int tid  = threadIdx.x;
    const int lane = tid & 31, w = tid >> 5;
    const int i    = blockIdx.x * T1 + tid;
    const float m  = read_margin(marginp);
    const float pw = pw_[0];

    float p = 0.f, bce = 0.f;
    bool pos = false, neg = false;
    if (i < n) {
        p = preds[i];
        const bool fl = (labels[i] > 0.5f);
        pos = fl; neg = !fl;
        const float x  = logits[i];
        const float t  = targets[i];
        const float mv = fmaxf(-x, 0.0f);
        const float sp = __logf(__expf(-mv) + __expf(-x - mv)) + mv;
        bce = (1.0f - t) * x + (1.0f + (pw - 1.0f) * t) * sp;
    }

    // n1: one atomic per warp
    const unsigned bp = __ballot_sync(0xffffffffu, pos);
    if (lane == 0 && bp) atomicAdd(&g_n1, __popc(bp));

    // binned scatter (in-bin order irrelevant: sums commute)
    if (neg) {
        const float c  = m + p;
        const int   ib = bin_of(c);
        const int  idx = atomicAdd(&g_bc[ib], 1);
        if (idx < CAP) {
            g_bins[ib * CAP + idx] = c;
            atomicAdd(&g_bs[ib], c);
        } else {
            const int oi = atomicAdd(&g_ovfCnt, 1);
            if (oi < MAXB) g_ovf[oi] = c;
        }
    }

    // BCE block reduce -> one plain store per block
    double d = (double)bce;
    #pragma unroll
    for (int off = 16; off; off >>= 1)
        d += __shfl_down_sync(0xffffffffu, d, off);
    __shared__ double wb[8];
    if (lane == 0) wb[w] = d;
    __syncthreads();
    if (tid == 0) {
        double s = 0.0;
        #pragma unroll
        for (int k = 0; k < 8; k++) s += wb[k];
        g_bceB[blockIdx.x] = s;
    }

    // ---- last-finishing block: suffix scan of the 256 bins ----------------
    __threadfence();
    __shared__ int isLast;
    if (tid == 0)
        isLast = (atomicAdd(&g_done1, 1u) == gridDim.x - 1u) ? 1 : 0;
    __syncthreads();
    if (!isLast) return;

    __shared__ double sS[NBIN + 1];
    __shared__ int    sC[NBIN + 1];
    if (tid < NBIN) {
        sC[tid] = min(*(volatile int*)&g_bc[tid], CAP);
        sS[tid] = (double)*(volatile float*)&g_bs[tid];
    }
    if (tid == 0) { sS[NBIN] = 0.0; sC[NBIN] = 0; }
    __syncthreads();
    for (int off = 1; off < NBIN; off <<= 1) {
        double vS = 0.0; int vC = 0;
        if (tid < NBIN && tid + off < NBIN) { vS = sS[tid + off]; vC = sC[tid + off]; }
        __syncthreads();
        if (tid < NBIN) { sS[tid] += vS; sC[tid] += vC; }
        __syncthreads();
    }
    // [NBIN] entry is statically 0 in global and must stay 0 -> only 0..NBIN-1
    if (tid < NBIN) { g_sufS[tid] = sS[tid]; g_sufC[tid] = sC[tid]; }
}

// ---------------------------------------------------------------------------
// Kernel 2: pure per-element eval; last block finalizes + resets.
// ---------------------------------------------------------------------------
__global__ void __launch_bounds__(T2)
k2(const float* __restrict__ preds, const float* __restrict__ labels,
   int n, int nb1, const void* __restrict__ marginp, float* __restrict__ out)
{
    const int tid  = threadIdx.x;
    const int lane = tid & 31, w = tid >> 5;
    const float m  = read_margin(marginp);

    const int i = blockIdx.x * T2 + tid;
    double dacc = 0.0;
    if (i < n && labels[i] > 0.5f) {
        const float a  = preds[i];
        const int   ka = bin_of(a);
        // strictly-higher bins: closed form (every c there satisfies c >= a)
        dacc = g_sufS[ka + 1] - (double)a * (double)g_sufC[ka + 1];
        // same-bin exact eval (L2-hot list, ~16 items avg; unrolled -> MLP)
        const int cnt  = min(g_bc[ka], CAP);
        const int base = ka * CAP;
        float part = 0.f;
        #pragma unroll 8
        for (int j = 0; j < cnt; j++)
            part += fmaxf(g_bins[base + j] - a, 0.f);
        // overflow list (normally empty)
        const int oc = min(g_ovfCnt, MAXB);
        for (int j = 0; j < oc; j++)
            part += fmaxf(g_ovf[j] - a, 0.f);
        dacc += (double)part;
    }

    // block reduce (4 warps) + publish
    #pragma unroll
    for (int off = 16; off; off >>= 1)
        dacc += __shfl_down_sync(0xffffffffu, dacc, off);
    __shared__ double wred[4];
    if (lane == 0) wred[w] = dacc;
    __syncthreads();
    __shared__ int isLast;
    if (tid == 0) {
        double s = wred[0] + wred[1] + wred[2] + wred[3];
        g_mixB[blockIdx.x] = s;
        __threadfence();
        isLast = (atomicAdd(&g_done2, 1u) == gridDim.x - 1u) ? 1 : 0;
    }
    __syncthreads();

    // ---- last block: final reduce + outputs + reset -----------------------
    if (isLast) {
        const int gb = gridDim.x;
        double fm = 0.0, fb = 0.0;
        for (int j = tid; j < gb; j += T2)  fm += __ldcg(&g_mixB[j]);
        for (int j = tid; j < nb1; j += T2) fb += __ldcg(&g_bceB[j]);
        #pragma unroll
        for (int off = 16; off; off >>= 1) {
            fm += __shfl_down_sync(0xffffffffu, fm, off);
            fb += __shfl_down_sync(0xffffffffu, fb, off);
        }
        __shared__ double zm[4], zb[4];
        if (lane == 0) { zm[w] = fm; zb[w] = fb; }
        __syncthreads();
        if (tid == 0) {
            const double sm = zm[0] + zm[1] + zm[2] + zm[3];
            const double sb = zb[0] + zb[1] + zb[2] + zb[3];
            const int    n1  = g_n1;
            const double dn1 = (double)n1, dn0 = (double)(n - n1);
            const double eqPairs = 0.5 * (dn1 * (dn1 - 1.0) + dn0 * (dn0 - 1.0));
            const double mm = (m > 0.0f) ? (double)m : 0.0;
            out[0] = (float)((mm * eqPairs + sm) / (double)n);
            out[1] = (float)(sb / (double)n);
        }
        __syncthreads();
        // reset persistent state for next graph replay
        for (int j = tid; j < NBIN; j += T2) { g_bc[j] = 0; g_bs[j] = 0.f; }
        if (tid == 0) { g_ovfCnt = 0; g_n1 = 0; g_done1 = 0u; g_done2 = 0u; }
    }
}

// ---------------------------------------------------------------------------
extern "C" void kernel_launch(void* const* d_in, const int* in_sizes, int n_in,
                              void* d_out, int out_size)
{
    const float* preds   = (const float*)d_in[0];
    const float* labels  = (const float*)d_in[1];
    const float* logits  = (const float*)d_in[2];
    const float* targets = (const float*)d_in[3];
    const float* pw      = (const float*)d_in[4];
    const void*  marginp = (n_in >= 6) ? d_in[5] : nullptr;
    const int n = in_sizes[0];
    float* out = (float*)d_out;

    const int g1 = min((n + T1 - 1) / T1, G1MAX);
    const int g2 = min((n + T2 - 1) / T2, G2MAX);
    k1<<<g1, T1>>>(preds, labels, logits, targets, pw, n, marginp);
    k2<<<g2, T2>>>(preds, labels, n, g1, marginp, out);
}

// round 12
// speedup vs baseline: 1.9261x; 1.1167x over previous
#include <cuda_runtime.h>
#include <math.h>

// ----------------------------------------------------------------------------
// margin ranking loss (all i<j pairs) + weighted BCE, B=8192, labels in {0,1}.
//   equal-label pairs: relu(m) each -> closed form from n1
//   mixed pairs:       relu((m + p_neg) - p_pos)
// Exact binned algorithm on a 1024-bin grid (clamped edge bins):
//   bin(c) > bin(a)  -> contributes (c - a)  -> suffix count/sum, O(1)/a
//   bin(c) == bin(a) -> exact relu vs bin list (~15 items, 4-chain MLP scan)
//   bin(c) < bin(a)  -> 0
// Overflowing bins spill to an exact-eval list -> exact for any input.
// k1: BCE + n1 + binned scatter; LAST block builds 16B/bin packed records
//     {sufS(b+1), sufC(b+1), cnt(b)} so k2 needs ONE LDG.128 per element.
// k2: per-element eval + final reduction/outputs/reset.
// ----------------------------------------------------------------------------

#define T1    256
#define G1MAX 64
#define T2    128
#define G2MAX 64
#define MAXB  8192
#define NBIN  1024
#define BPT   4                 // bins per thread in the scan (NBIN / T1)
#define CAP   48
#define BLO   (-6.0f)
#define BHI   (7.0f)
#define INVW  ((float)NBIN / (BHI - BLO))

// scratch (allocation-free rule: __device__ globals)
__device__ int      g_bc[NBIN];            // bin attempt counts
__device__ float    g_bs[NBIN];            // bin sums (stored items only)
__device__ float    g_bins[NBIN * CAP];    // stored c values per bin
__device__ float    g_ovf[MAXB];           // overflow list (normally empty)
__device__ int      g_ovfCnt = 0;
__device__ int      g_n1     = 0;
__device__ double2  g_rec[NBIN];           // {sufS(b+1), pack(cnt_b, sufC(b+1))}
__device__ double   g_bceB[G1MAX];
__device__ double   g_mixB[G2MAX];
__device__ unsigned g_done1  = 0;
__device__ unsigned g_done2  = 0;

__device__ __forceinline__ float read_margin(const void* p) {
    if (p == nullptr) return 1.0f;
    int v = *(const int*)p;
    if (v >= -1000000 && v <= 1000000) return (float)v;   // int scalar
    return __int_as_float(v);                             // float bits
}

__device__ __forceinline__ int bin_of(float x) {
    int b = (int)floorf((x - BLO) * INVW);
    return max(0, min(NBIN - 1, b));
}

// ---------------------------------------------------------------------------
// Kernel 1: BCE partials, n1, binned scatter; last block: record build.
// ---------------------------------------------------------------------------
__global__ void __launch_bounds__(T1)
k1(const float* __restrict__ preds,  const float* __restrict__ labels,
   const float* __restrict__ logits, const float* __restrict__ targets,
   const float* __restrict__ pw_, int n, const void* __restrict__ marginp)
{
    const int tid  = threadIdx.x;
    const int lane = tid & 31, w = tid >> 5;
    const int i    = blockIdx.x * T1 + tid;
    const float m  = read_margin(marginp);
    const float pw = pw_[0];

    float p = 0.f, bce = 0.f;
    bool pos = false, neg = false;
    if (i < n) {
        p = preds[i];
        const bool fl = (labels[i] > 0.5f);
        pos = fl; neg = !fl;
        const float x  = logits[i];
        const float t  = targets[i];
        const float mv = fmaxf(-x, 0.0f);
        const float sp = __logf(__expf(-mv) + __expf(-x - mv)) + mv;
        bce = (1.0f - t) * x + (1.0f + (pw - 1.0f) * t) * sp;
    }

    // n1: one atomic per warp
    const unsigned bp = __ballot_sync(0xffffffffu, pos);
    if (lane == 0 && bp) atomicAdd(&g_n1, __popc(bp));

    // binned scatter (in-bin order irrelevant: sums commute)
    if (neg) {
        const float c  = m + p;
        const int   ib = bin_of(c);
        const int  idx = atomicAdd(&g_bc[ib], 1);
        if (idx < CAP) {
            g_bins[ib * CAP + idx] = c;
            atomicAdd(&g_bs[ib], c);
        } else {
            const int oi = atomicAdd(&g_ovfCnt, 1);
            if (oi < MAXB) g_ovf[oi] = c;
        }
    }

    // BCE block reduce -> one plain store per block
    double d = (double)bce;
    #pragma unroll
    for (int off = 16; off; off >>= 1)
        d += __shfl_down_sync(0xffffffffu, d, off);
    __shared__ double wb[8];
    if (lane == 0) wb[w] = d;
    __syncthreads();
    if (tid == 0) {
        double s = 0.0;
        #pragma unroll
        for (int k = 0; k < 8; k++) s += wb[k];
        g_bceB[blockIdx.x] = s;
    }

    // ---- last-finishing block: suffix scan + packed record build ----------
    __threadfence();
    __shared__ int isLast;
    if (tid == 0)
        isLast = (atomicAdd(&g_done1, 1u) == gridDim.x - 1u) ? 1 : 0;
    __syncthreads();
    if (!isLast) return;

    // each thread owns bins [BPT*tid, BPT*tid+BPT)
    double v[BPT]; int c[BPT];
    #pragma unroll
    for (int k = 0; k < BPT; k++) {
        const int b = BPT * tid + k;
        c[k] = min(*(volatile int*)&g_bc[b], CAP);
        v[k] = (double)*(volatile float*)&g_bs[b];
    }
    double Tt = 0.0; int Ct = 0;
    #pragma unroll
    for (int k = 0; k < BPT; k++) { Tt += v[k]; Ct += c[k]; }

    // inclusive SUFFIX scan of thread totals (Hillis-Steele, 8 passes)
    __shared__ double tS[T1];
    __shared__ int    tC[T1];
    tS[tid] = Tt; tC[tid] = Ct;
    __syncthreads();
    for (int off = 1; off < T1; off <<= 1) {
        double aS = 0.0; int aC = 0;
        if (tid + off < T1) { aS = tS[tid + off]; aC = tC[tid + off]; }
        __syncthreads();
        tS[tid] += aS; tC[tid] += aC;
        __syncthreads();
    }
    const double tailS = tS[tid] - Tt;      // strictly-after this thread
    const int    tailC = tC[tid] - Ct;

    // per-bin records: suf(b+1) = tail + sum of own bins with index > k
    double accS = tailS; int accC = tailC;
    #pragma unroll
    for (int k = BPT - 1; k >= 0; k--) {
        const int b = BPT * tid + k;
        g_rec[b] = make_double2(accS, __hiloint2double(c[k], accC));
        accS += v[k]; accC += c[k];
    }
}

// ---------------------------------------------------------------------------
// Kernel 2: per-element eval (1 LDG.128 record + short MLP list scan);
// last block finalizes outputs and resets persistent state.
// ---------------------------------------------------------------------------
__global__ void __launch_bounds__(T2)
k2(const float* __restrict__ preds, const float* __restrict__ labels,
   int n, int nb1, const void* __restrict__ marginp, float* __restrict__ out)
{
    const int tid  = threadIdx.x;
    const int lane = tid & 31, w = tid >> 5;
    const float m  = read_margin(marginp);

    const int i = blockIdx.x * T2 + tid;
    double dacc = 0.0;
    if (i < n && labels[i] > 0.5f) {
        const float a  = preds[i];
        const int   ka = bin_of(a);
        const double2 r = g_rec[ka];                 // ONE 16B load
        const int sufC = __double2loint(r.y);
        const int cnt  = __double2hiint(r.y);
        // strictly-higher bins: closed form (every c there satisfies c >= a)
        dacc = r.x - (double)a * (double)sufC;
        // same-bin exact eval: 4 independent chains, unroll-by-4 -> MLP
        const float* lp = &g_bins[ka * CAP];
        float p0 = 0.f, p1 = 0.f, p2 = 0.f, p3 = 0.f;
        int j = 0;
        for (; j + 4 <= cnt; j += 4) {
            p0 += fmaxf(lp[j]     - a, 0.f);
            p1 += fmaxf(lp[j + 1] - a, 0.f);
            p2 += fmaxf(lp[j + 2] - a, 0.f);
            p3 += fmaxf(lp[j + 3] - a, 0.f);
        }
        for (; j < cnt; j++) p0 += fmaxf(lp[j] - a, 0.f);
        // overflow list (normally empty)
        const int oc = min(g_ovfCnt, MAXB);
        for (int j2 = 0; j2 < oc; j2++) p1 += fmaxf(g_ovf[j2] - a, 0.f);
        dacc += (double)((p0 + p1) + (p2 + p3));
    }

    // block reduce (4 warps) + publish
    #pragma unroll
    for (int off = 16; off; off >>= 1)
        dacc += __shfl_down_sync(0xffffffffu, dacc, off);
    __shared__ double wred[4];
    if (lane == 0) wred[w] = dacc;
    __syncthreads();
    __shared__ int isLast;
    if (tid == 0) {
        g_mixB[blockIdx.x] = wred[0] + wred[1] + wred[2] + wred[3];
        __threadfence();
        isLast = (atomicAdd(&g_done2, 1u) == gridDim.x - 1u) ? 1 : 0;
    }
    __syncthreads();

    // ---- last block: final reduce + outputs + reset -----------------------
    if (isLast) {
        const int gb = gridDim.x;
        double fm = 0.0, fb = 0.0;
        for (int j = tid; j < gb; j += T2)  fm += __ldcg(&g_mixB[j]);
        for (int j = tid; j < nb1; j += T2) fb += __ldcg(&g_bceB[j]);
        #pragma unroll
        for (int off = 16; off; off >>= 1) {
            fm += __shfl_down_sync(0xffffffffu, fm, off);
            fb += __shfl_down_sync(0xffffffffu, fb, off);
        }
        __shared__ double zm[4], zb[4];
        if (lane == 0) { zm[w] = fm; zb[w] = fb; }
        __syncthreads();
        if (tid == 0) {
            const double sm = zm[0] + zm[1] + zm[2] + zm[3];
            const double sb = zb[0] + zb[1] + zb[2] + zb[3];
            const int    n1  = g_n1;
            const double dn1 = (double)n1, dn0 = (double)(n - n1);
            const double eqPairs = 0.5 * (dn1 * (dn1 - 1.0) + dn0 * (dn0 - 1.0));
            const double mm = (m > 0.0f) ? (double)m : 0.0;
            out[0] = (float)((mm * eqPairs + sm) / (double)n);
            out[1] = (float)(sb / (double)n);
        }
        __syncthreads();
        // reset persistent state for next graph replay
        for (int j = tid; j < NBIN; j += T2) { g_bc[j] = 0; g_bs[j] = 0.f; }
        if (tid == 0) { g_ovfCnt = 0; g_n1 = 0; g_done1 = 0u; g_done2 = 0u; }
    }
}

// ---------------------------------------------------------------------------
extern "C" void kernel_launch(void* const* d_in, const int* in_sizes, int n_in,
                              void* d_out, int out_size)
{
    const float* preds   = (const float*)d_in[0];
    const float* labels  = (const float*)d_in[1];
    const float* logits  = (const float*)d_in[2];
    const float* targets = (const float*)d_in[3];
    const float* pw      = (const float*)d_in[4];
    const void*  marginp = (n_in >= 6) ? d_in[5] : nullptr;
    const int n = in_sizes[0];
    float* out = (float*)d_out;

    const int g1 = min((n + T1 - 1) / T1, G1MAX);
    const int g2 = min((n + T2 - 1) / T2, G2MAX);
    k1<<<g1, T1>>>(preds, labels, logits, targets, pw, n, marginp);
    k2<<<g2, T2>>>(preds, labels, n, g1, marginp, out);
}